// round 13
// baseline (speedup 1.0000x reference)
#include <cuda_runtime.h>
#include <math.h>

// Problem constants (fixed by the dataset)
#define BB 4
#define NN 512
#define NZV 95
#define TBL (NZV * 25)    // 2375 entries per zi table
#define NCH 36            // cn j-chunks per batch (BB*NCH = 144 slots)
#define NITEMS (NZV * BB) // 380 energy work items (it = zi*4 + b)
#define GRID 148
#define NT 1024           // threads per block

#define F_A1   0.4145f
#define F_A2   4.8593f
#define F_S8   1.2177f
#define F_K1   16.0f
#define F_K3   4.0f
#define F_LOG2E 1.4426950408889634f
#define F_K3L   (F_K3 * F_LOG2E)
#define F_BOHR 1.8897261258369282f
#define F_BOHR2 (F_BOHR * F_BOHR)
#define F_H2EV 27.211386245988f

// Global scratch (allocation-free rules: __device__ globals, zero-init)
__device__ float    g_cnp[BB * NCH * 2 * NN]; // cn partials per (chunk,half)
__device__ float4   g_tab[NZV * TBL];      // packed {A,B,G,c6f+c6r} per zi
__device__ float4   g_spos[BB * NN];       // species-sorted (x,y,z,cn)
__device__ float    g_srr[BB * NN];        // sorted r4r2[z]
__device__ int      g_szj[BB * NN];        // sorted species
__device__ int      g_perm[BB * NN];       // atom -> sorted slot
__device__ int      g_goff[BB * 96];       // species bucket offsets
__device__ float    g_partial[NITEMS];     // per-item energy partials
__device__ unsigned g_bar[3];              // monotonic barrier counters
__device__ unsigned g_ticket;              // energy work queue (reset at end)

__device__ __forceinline__ int clampz(int z) {
    z = z < 0 ? 0 : z;
    return z > (NZV - 1) ? (NZV - 1) : z;
}

__device__ __forceinline__ float ex2f(float x) {
    float r;
    asm("ex2.approx.ftz.f32 %0, %1;" : "=f"(r) : "f"(x));
    return r;
}

// Grid-wide barrier. Monotonic counter (wrap-safe compare) so it needs no
// reset across graph replays. All GRID blocks are co-resident (1 wave).
__device__ __forceinline__ void gsync(int id) {
    __syncthreads();
    if (threadIdx.x == 0) {
        __threadfence();
        unsigned old = atomicAdd(&g_bar[id], 1u);
        unsigned target = old + (GRID - old % GRID);
        while ((int)(*(volatile unsigned*)&g_bar[id] - target) < 0)
            __nanosleep(64);
        __threadfence();
    }
    __syncthreads();
}

__global__ __launch_bounds__(NT, 1) void fused_kernel(
    const float* __restrict__ coord,
    const int*   __restrict__ numbers,
    const float* __restrict__ rcov,
    const float* __restrict__ r4r2,
    const float* __restrict__ c6ab,
    const float* __restrict__ cn_ref,
    float* __restrict__ out)
{
    __shared__ float4 s_tab[TBL];     // energy tables {A,B,G,c6s}  (38 KB)
    __shared__ float4 s_j[16];        // cn chunk stage
    __shared__ int    s_wh[16][96];   // perm: per-warp species histogram
    __shared__ int    s_tot[96];
    __shared__ int    s_off[96];
    __shared__ float  s_red[32];
    __shared__ double s_dred[32];
    __shared__ int    s_item;

    int t    = threadIdx.x;
    int blk  = blockIdx.x;
    int wid  = t >> 5, lane = t & 31;
    int jslot = t & (NN - 1);          // j index (0..511)
    int half  = t >> 9;                // i-parity (0/1)

    // =====================================================================
    // Phase 1a (all blocks): build packed energy table g_tab[zi][a*25+r].
    // Weights are direction-symmetric: w_ij(k,l) == w_ji(l,k), wsum equal.
    // Store COMBINED numerator c6s = c6ab[zi][a][k,l] + c6ab[a][zi][l,k];
    // one weighted sum then yields c6(i,j)+c6(j,i) exactly.
    //   w = exp2(A*cni + B*cnj + G + D)
    // =====================================================================
    {
        const int total = NZV * TBL;
        for (int q = blk * NT + t; q < total; q += GRID * NT) {
            int zi = q / TBL;
            int r  = q - zi * TBL;      // a*25 + rem
            int a  = r / 25;
            int rem = r - a * 25;
            int k = rem / 5, l = rem - 5 * k;
            float av  = __ldg(&cn_ref[((size_t)zi * NZV + a) * 25 + rem]);
            float bv  = __ldg(&cn_ref[((size_t)a * NZV + zi) * 25 + l * 5 + k]);
            float c6f = __ldg(&c6ab  [((size_t)zi * NZV + a) * 25 + rem]);
            float c6r = __ldg(&c6ab  [((size_t)a * NZV + zi) * 25 + l * 5 + k]);
            float A  = 2.0f * F_K3L * av;
            float Bv = 2.0f * F_K3L * bv;
            float G  = -F_K3L * (av * av + bv * bv);
            if (c6f <= 0.0f) G = -__int_as_float(0x7f800000);  // dead here (c6ab>0)
            g_tab[q] = make_float4(A, Bv, G, c6f + c6r);
        }
    }

    // =====================================================================
    // Phase 1b: slots 0..143 = CN chunk partials; 144..147 = permutation
    // =====================================================================
    if (blk < BB * NCH) {
        int b = blk & 3;              // slot = c*4 + b
        int c = blk >> 2;
        int j0 = (c * NN) / NCH;
        int j1 = ((c + 1) * NN) / NCH;
        int cnt = j1 - j0;

        if (t < cnt) {
            int j = j0 + t;
            const float* cb = coord + ((size_t)b * NN + j) * 3;
            s_j[t] = make_float4(cb[0], cb[1], cb[2],
                                 __ldg(&rcov[clampz(numbers[b * NN + j])]));
        }
        __syncthreads();

        int i = jslot;
        const float* ci = coord + ((size_t)b * NN + i) * 3;
        float xi = ci[0], yi = ci[1], zi_ = ci[2];
        float rci = __ldg(&rcov[clampz(numbers[b * NN + i])]);

        float sum = 0.0f;
        for (int jj = half; jj < cnt; jj += 2) {
            int j = j0 + jj;
            if (j == i) continue;
            float4 p = s_j[jj];
            float dx = xi - p.x, dy = yi - p.y, dz = zi_ - p.z;
            float r2 = dx * dx + dy * dy + dz * dz;
            float r_ang = sqrtf(r2);
            if (r_ang > 15.0f) continue;
            float rco = rci + p.w;
            float a = F_K1 * (__fdividef(rco, r_ang * F_BOHR) - 1.0f);
            sum += 1.0f / (1.0f + __expf(-a));   // sigmoid(a)
        }
        g_cnp[(((size_t)b * NCH + c) * 2 + half) * NN + i] = sum;
    } else {
        // permutation for batch b (deterministic stable species sort)
        int b = blk - BB * NCH;
        int z = 0;
        if (t < NN) z = clampz(numbers[b * NN + t]);

        for (int q = t; q < 16 * 96; q += NT) (&s_wh[0][0])[q] = 0;
        __syncthreads();

        if (t < NN) {
            unsigned m = __match_any_sync(0xffffffffu, z);
            int intra = __popc(m & ((1u << lane) - 1u));
            int leader = __ffs(m) - 1;
            if (lane == leader) s_wh[wid][z] = __popc(m);
            g_perm[b * NN + t] = intra;   // stash intra rank temporarily
        }
        __syncthreads();

        if (t < 95) {
            int acc = 0;
            #pragma unroll
            for (int w = 0; w < 16; w++) { int c_ = s_wh[w][t]; s_wh[w][t] = acc; acc += c_; }
            s_tot[t] = acc;
        }
        __syncthreads();
        if (t == 0) {
            int acc = 0;
            for (int a = 0; a < NZV; a++) { s_off[a] = acc; acc += s_tot[a]; }
            s_off[95] = acc;   // == NN
        }
        __syncthreads();

        if (t < NN)
            g_perm[b * NN + t] = s_off[z] + s_wh[wid][z] + g_perm[b * NN + t];
        if (t < 96) g_goff[b * 96 + t] = s_off[t];
    }

    gsync(0);

    // =====================================================================
    // Phase 2: blocks 0..3 gather CN sums + scatter sorted records
    // =====================================================================
    if (blk < BB && t < NN) {
        int b = blk;
        float cn = 0.0f;
        #pragma unroll
        for (int q = 0; q < NCH * 2; q++)
            cn += g_cnp[((size_t)b * NCH * 2 + q) * NN + t];

        int z = clampz(numbers[b * NN + t]);
        int p = g_perm[b * NN + t];
        const float* ci = coord + ((size_t)b * NN + t) * 3;
        g_spos[b * NN + p] = make_float4(ci[0], ci[1], ci[2], cn);
        g_srr [b * NN + p] = __ldg(&r4r2[z]);
        g_szj [b * NN + p] = z;
    }

    gsync(1);

    // =====================================================================
    // Phase 3: energy items via dynamic ticket queue; item = zi*4 + b.
    // BALANCED half-shell symmetry: pair (sp, jslot) handled by this thread
    // iff d = (jslot - sp) mod 512 is in [1,255], or d==256 with jslot < sp.
    // Exactly-once per unordered pair; every warp active for ~half the i's
    // (warp-coherent: sp uniform, warp spans 32 consecutive jslots).
    // Combined table gives e(i,j)+e(j,i) per pair.
    // =====================================================================
    int wbase = (wid & 15) << 5;           // first jslot in my warp

    while (true) {
        __syncthreads();                   // protects s_tab/s_red reuse
        if (t == 0) s_item = (int)atomicAdd(&g_ticket, 1u);
        __syncthreads();
        int it = s_item;
        if (it >= NITEMS) break;

        int zi = it >> 2;
        int b  = it & 3;

        int off = __ldg(&g_goff[b * 96 + zi]);
        int end = __ldg(&g_goff[b * 96 + zi + 1]);
        int n   = end - off;
        if (n <= 0) {
            if (t == 0) g_partial[it] = 0.0f;
            continue;
        }

        // Stage packed table: coalesced float4 copy from g_tab
        {
            const float4* gt = g_tab + (size_t)zi * TBL;
            for (int q = t; q < TBL; q += NT) s_tab[q] = __ldg(&gt[q]);
        }
        __syncthreads();

        // my j-side data (fixed for this item)
        float4 pj  = __ldg(&g_spos[b * NN + jslot]);
        float  rrj = __ldg(&g_srr [b * NN + jslot]);
        int    zj  = __ldg(&g_szj [b * NN + jslot]);
        float  cnj_v = pj.w;
        float  Lcnj2 = F_K3L * cnj_v * cnj_v;
        const float4* ptab = s_tab + zj * 25;

        float esum = 0.0f;
        for (int ii = half; ii < n; ii += 2) {
            int sp = off + ii;                  // block-uniform
            // warp-uniform skip: warp covers d in [bd, bd+31] (mod 512);
            // inactive iff the whole span lies in [257, 511]
            int bd = (wbase - sp) & 511;
            if (bd >= 257 && bd <= 480) continue;

            float4 pi  = __ldg(&g_spos[b * NN + sp]);
            float  rri = __ldg(&g_srr [b * NN + sp]);

            float dx = pi.x - pj.x, dy = pi.y - pj.y, dz = pi.z - pj.z;
            float r2 = dx * dx + dy * dy + dz * dz;
            float ra = sqrtf(r2);

            int d = (jslot - sp) & 511;
            bool mine = (d >= 1 && d <= 255) || (d == 256 && jslot < sp);
            bool valid = mine && (ra <= 15.0f);

            float cni_v = pi.w;
            float Dp = fmaf(-F_K3L, cni_v * cni_v, -Lcnj2);

            float w0 = 0.0f, w1 = 0.0f, c60 = 0.0f, c61 = 0.0f;
            #pragma unroll
            for (int r = 0; r < 25; r++) {
                float4 tv = ptab[r];
                float arg = fmaf(tv.x, cni_v, fmaf(tv.y, cnj_v, tv.z)) + Dp;
                float w = ex2f(arg);
                if (r & 1) { w1 += w; c61 = fmaf(tv.w, w, c61); }
                else       { w0 += w; c60 = fmaf(tv.w, w, c60); }
            }
            // c6v = c6(i,j) + c6(j,i)  (combined numerator, shared wsum)
            float c6v = __fdividef(c60 + c61, w0 + w1 + 1e-20f);

            float rr = rri * rrj;
            float c8 = 3.0f * c6v * rr;        // = c8(i,j)+c8(j,i)
            float r0v = sqrtf(3.0f * rr);
            float fv = fmaf(F_A1, r0v, F_A2);
            float f2 = fv * fv;
            float f6 = f2 * f2 * f2;
            float f8 = f6 * f2;

            float rb2 = r2 * F_BOHR2;
            float r6 = rb2 * rb2 * rb2;
            float r8 = r6 * rb2;

            // e = e(i,j) + e(j,i)
            float e = __fdividef(c6v, r6 + f6) + F_S8 * __fdividef(c8, r8 + f8);

            float x = __saturatef((ra - 12.0f) * (1.0f / 3.0f));
            float sw = 1.0f - x * x * (3.0f - 2.0f * x);

            esum = fmaf(e * sw, valid ? 1.0f : 0.0f, esum);
        }

        // deterministic block reduce -> g_partial[it]
        #pragma unroll
        for (int o = 16; o > 0; o >>= 1) esum += __shfl_down_sync(0xffffffffu, esum, o);
        if (lane == 0) s_red[wid] = esum;
        __syncthreads();
        if (t < 32) {
            float v = s_red[t];
            #pragma unroll
            for (int o = 16; o > 0; o >>= 1) v += __shfl_down_sync(0xffffffffu, v, o);
            if (t == 0) g_partial[it] = v;
        }
    }

    gsync(2);

    // =====================================================================
    // Phase 4: block 0 finalizes (fixed order, double precision). Factor -0.5:
    // each unordered pair contributed e(i,j)+e(j,i). Resets queue.
    // =====================================================================
    if (blk == 0) {
        if (t == 0) g_ticket = 0;              // ready for next graph replay
        for (int b2 = 0; b2 < BB; b2++) {
            double v = 0.0;
            if (t < NZV)
                v = (double)((volatile float*)g_partial)[t * 4 + b2];
            #pragma unroll
            for (int o = 16; o > 0; o >>= 1) v += __shfl_down_sync(0xffffffffu, v, o);
            if (lane == 0) s_dred[wid] = v;
            __syncthreads();
            if (t < 32) {
                double u = (t < 4) ? s_dred[t] : 0.0;  // only warps 0..3 hold data
                #pragma unroll
                for (int o = 16; o > 0; o >>= 1) u += __shfl_down_sync(0xffffffffu, u, o);
                if (t == 0) out[b2] = (float)(-0.5 * u * (double)F_H2EV);
            }
            __syncthreads();
        }
    }
}

extern "C" void kernel_launch(void* const* d_in, const int* in_sizes, int n_in,
                              void* d_out, int out_size)
{
    const float* coord   = (const float*)d_in[0];
    const int*   numbers = (const int*)  d_in[1];
    const float* rcov    = (const float*)d_in[2];
    const float* r4r2    = (const float*)d_in[3];
    const float* c6ab    = (const float*)d_in[4];
    const float* cn_ref  = (const float*)d_in[5];
    float* out = (float*)d_out;

    fused_kernel<<<GRID, NT>>>(coord, numbers, rcov, r4r2, c6ab, cn_ref, out);
}

// round 14
// speedup vs baseline: 1.2541x; 1.2541x over previous
#include <cuda_runtime.h>
#include <math.h>

// Problem constants (fixed by the dataset)
#define BB 4
#define NN 512
#define NZV 95
#define TBL (NZV * 25)    // 2375 entries per zi table
#define NCH 72            // cn j-chunks per batch (BB*NCH = 288 slots)
#define NITEMS (NZV * BB) // 380 energy work items (it = zi*4 + b)
#define GRID 296          // 2 blocks per SM, all co-resident
#define NT 512            // threads per block

#define F_A1   0.4145f
#define F_A2   4.8593f
#define F_S8   1.2177f
#define F_K1   16.0f
#define F_K3   4.0f
#define F_LOG2E 1.4426950408889634f
#define F_K3L   (F_K3 * F_LOG2E)
#define F_BOHR 1.8897261258369282f
#define F_BOHR2 (F_BOHR * F_BOHR)
#define F_H2EV 27.211386245988f

// Global scratch (allocation-free rules: __device__ globals, zero-init)
__device__ float    g_cnp[BB * NCH * NN];  // cn partials per chunk
__device__ float4   g_tab[NZV * TBL];      // packed {A,B,G,c6f+c6r} per zi
__device__ float4   g_spos[BB * NN];       // species-sorted (x,y,z,cn)
__device__ float    g_srr[BB * NN];        // sorted r4r2[z]
__device__ int      g_szj[BB * NN];        // sorted species
__device__ int      g_perm[BB * NN];       // atom -> sorted slot
__device__ int      g_goff[BB * 96];       // species bucket offsets
__device__ float    g_partial[NITEMS];     // per-item energy partials
__device__ unsigned g_bar[3];              // monotonic barrier counters
__device__ unsigned g_ticket;              // energy work queue (reset at end)

__device__ __forceinline__ int clampz(int z) {
    z = z < 0 ? 0 : z;
    return z > (NZV - 1) ? (NZV - 1) : z;
}

__device__ __forceinline__ float ex2f(float x) {
    float r;
    asm("ex2.approx.ftz.f32 %0, %1;" : "=f"(r) : "f"(x));
    return r;
}

// Grid-wide barrier. Monotonic counter (wrap-safe compare) so it needs no
// reset across graph replays. All GRID blocks are co-resident (2 per SM,
// enforced by __launch_bounds__(512,2) -> <=64 regs, 2x46KB smem fits).
__device__ __forceinline__ void gsync(int id) {
    __syncthreads();
    if (threadIdx.x == 0) {
        __threadfence();
        unsigned old = atomicAdd(&g_bar[id], 1u);
        unsigned target = old + (GRID - old % GRID);
        while ((int)(*(volatile unsigned*)&g_bar[id] - target) < 0)
            __nanosleep(64);
        __threadfence();
    }
    __syncthreads();
}

__global__ __launch_bounds__(NT, 2) void fused_kernel(
    const float* __restrict__ coord,
    const int*   __restrict__ numbers,
    const float* __restrict__ rcov,
    const float* __restrict__ r4r2,
    const float* __restrict__ c6ab,
    const float* __restrict__ cn_ref,
    float* __restrict__ out)
{
    __shared__ float4 s_tab[TBL];     // energy tables {A,B,G,c6s}  (38 KB)
    __shared__ float4 s_j[8];         // cn chunk stage
    __shared__ int    s_wh[16][96];   // perm: per-warp species histogram
    __shared__ int    s_tot[96];
    __shared__ int    s_off[96];
    __shared__ float  s_red[16];
    __shared__ double s_dred[16];
    __shared__ int    s_item;

    int t    = threadIdx.x;
    int blk  = blockIdx.x;
    int wid  = t >> 5, lane = t & 31;
    int jslot = t;                     // j index (0..511)

    // =====================================================================
    // Phase 1a (all blocks): build packed energy table g_tab[zi][a*25+r].
    // Weights are direction-symmetric: w_ij(k,l) == w_ji(l,k), wsum equal.
    // Store COMBINED numerator c6s = c6ab[zi][a][k,l] + c6ab[a][zi][l,k];
    // one weighted sum then yields c6(i,j)+c6(j,i) exactly.
    //   w = exp2(A*cni + B*cnj + G + D)
    // =====================================================================
    {
        const int total = NZV * TBL;
        for (int q = blk * NT + t; q < total; q += GRID * NT) {
            int zi = q / TBL;
            int r  = q - zi * TBL;      // a*25 + rem
            int a  = r / 25;
            int rem = r - a * 25;
            int k = rem / 5, l = rem - 5 * k;
            float av  = __ldg(&cn_ref[((size_t)zi * NZV + a) * 25 + rem]);
            float bv  = __ldg(&cn_ref[((size_t)a * NZV + zi) * 25 + l * 5 + k]);
            float c6f = __ldg(&c6ab  [((size_t)zi * NZV + a) * 25 + rem]);
            float c6r = __ldg(&c6ab  [((size_t)a * NZV + zi) * 25 + l * 5 + k]);
            float A  = 2.0f * F_K3L * av;
            float Bv = 2.0f * F_K3L * bv;
            float G  = -F_K3L * (av * av + bv * bv);
            if (c6f <= 0.0f) G = -__int_as_float(0x7f800000);  // dead here (c6ab>0)
            g_tab[q] = make_float4(A, Bv, G, c6f + c6r);
        }
    }

    // =====================================================================
    // Phase 1b: slots 0..287 = CN chunk partials; 288..291 = permutation
    // =====================================================================
    if (blk < BB * NCH) {
        int b = blk & 3;              // slot = c*4 + b
        int c = blk >> 2;
        int j0 = (c * NN) / NCH;
        int j1 = ((c + 1) * NN) / NCH;
        int cnt = j1 - j0;            // 7 or 8

        if (t < cnt) {
            int j = j0 + t;
            const float* cb = coord + ((size_t)b * NN + j) * 3;
            s_j[t] = make_float4(cb[0], cb[1], cb[2],
                                 __ldg(&rcov[clampz(numbers[b * NN + j])]));
        }
        __syncthreads();

        int i = t;
        const float* ci = coord + ((size_t)b * NN + i) * 3;
        float xi = ci[0], yi = ci[1], zi_ = ci[2];
        float rci = __ldg(&rcov[clampz(numbers[b * NN + i])]);

        float sum = 0.0f;
        for (int jj = 0; jj < cnt; jj++) {
            int j = j0 + jj;
            if (j == i) continue;
            float4 p = s_j[jj];
            float dx = xi - p.x, dy = yi - p.y, dz = zi_ - p.z;
            float r2 = dx * dx + dy * dy + dz * dz;
            float r_ang = sqrtf(r2);
            if (r_ang > 15.0f) continue;
            float rco = rci + p.w;
            float a = F_K1 * (__fdividef(rco, r_ang * F_BOHR) - 1.0f);
            sum += 1.0f / (1.0f + __expf(-a));   // sigmoid(a)
        }
        g_cnp[((size_t)b * NCH + c) * NN + i] = sum;
    } else if (blk < BB * NCH + BB) {
        // permutation for batch b (deterministic stable species sort)
        int b = blk - BB * NCH;
        int z = clampz(numbers[b * NN + t]);

        for (int q = t; q < 16 * 96; q += NT) (&s_wh[0][0])[q] = 0;
        __syncthreads();

        unsigned m = __match_any_sync(0xffffffffu, z);
        int intra = __popc(m & ((1u << lane) - 1u));
        int leader = __ffs(m) - 1;
        if (lane == leader) s_wh[wid][z] = __popc(m);
        __syncthreads();

        if (t < 95) {
            int acc = 0;
            #pragma unroll
            for (int w = 0; w < 16; w++) { int c_ = s_wh[w][t]; s_wh[w][t] = acc; acc += c_; }
            s_tot[t] = acc;
        }
        __syncthreads();
        if (t == 0) {
            int acc = 0;
            for (int a = 0; a < NZV; a++) { s_off[a] = acc; acc += s_tot[a]; }
            s_off[95] = acc;   // == NN
        }
        __syncthreads();

        g_perm[b * NN + t] = s_off[z] + s_wh[wid][z] + intra;
        if (t < 96) g_goff[b * 96 + t] = s_off[t];
    }

    gsync(0);

    // =====================================================================
    // Phase 2: blocks 0..3 gather CN sums + scatter sorted records
    // =====================================================================
    if (blk < BB) {
        int b = blk;
        float cn = 0.0f;
        #pragma unroll
        for (int c = 0; c < NCH; c++)
            cn += g_cnp[((size_t)b * NCH + c) * NN + t];

        int z = clampz(numbers[b * NN + t]);
        int p = g_perm[b * NN + t];
        const float* ci = coord + ((size_t)b * NN + t) * 3;
        g_spos[b * NN + p] = make_float4(ci[0], ci[1], ci[2], cn);
        g_srr [b * NN + p] = __ldg(&r4r2[z]);
        g_szj [b * NN + p] = z;
    }

    gsync(1);

    // =====================================================================
    // Phase 3: energy items via dynamic ticket queue; item = zi*4 + b.
    // Triangle (sp < jslot), combined table -> e(i,j)+e(j,i) per pair.
    // 2-way i-unroll: both i's share the tv LDS + base FMA; 4 accum chains.
    // =====================================================================
    int wlast = (wid << 5) + 31;           // max jslot in my warp

    while (true) {
        __syncthreads();                   // protects s_tab/s_red reuse
        if (t == 0) s_item = (int)atomicAdd(&g_ticket, 1u);
        __syncthreads();
        int it = s_item;
        if (it >= NITEMS) break;

        int zi = it >> 2;
        int b  = it & 3;

        int off = __ldg(&g_goff[b * 96 + zi]);
        int end = __ldg(&g_goff[b * 96 + zi + 1]);
        int n   = end - off;
        if (n <= 0) {
            if (t == 0) g_partial[it] = 0.0f;
            continue;
        }

        // Stage packed table: coalesced float4 copy from g_tab
        {
            const float4* gt = g_tab + (size_t)zi * TBL;
            for (int q = t; q < TBL; q += NT) s_tab[q] = __ldg(&gt[q]);
        }
        __syncthreads();

        // my j-side data (fixed for this item)
        float4 pj  = __ldg(&g_spos[b * NN + jslot]);
        float  rrj = __ldg(&g_srr [b * NN + jslot]);
        int    zj  = __ldg(&g_szj [b * NN + jslot]);
        float  cnj_v = pj.w;
        float  Lcnj2 = F_K3L * cnj_v * cnj_v;
        const float4* ptab = s_tab + zj * 25;

        float esum = 0.0f;
        for (int ii = 0; ii < n; ii += 2) {
            int sp0 = off + ii;                 // block-uniform
            if (sp0 >= wlast) continue;         // warp-uniform skip (i<j only)
            int has1 = (ii + 1 < n);
            int sp1 = sp0 + has1;

            float4 pi0 = __ldg(&g_spos[b * NN + sp0]);
            float4 pi1 = __ldg(&g_spos[b * NN + sp1]);
            float  rri0 = __ldg(&g_srr[b * NN + sp0]);
            float  rri1 = __ldg(&g_srr[b * NN + sp1]);

            float dx0 = pi0.x - pj.x, dy0 = pi0.y - pj.y, dz0 = pi0.z - pj.z;
            float dx1 = pi1.x - pj.x, dy1 = pi1.y - pj.y, dz1 = pi1.z - pj.z;
            float r2_0 = dx0 * dx0 + dy0 * dy0 + dz0 * dz0;
            float r2_1 = dx1 * dx1 + dy1 * dy1 + dz1 * dz1;
            float ra0 = sqrtf(r2_0);
            float ra1 = sqrtf(r2_1);
            bool v0 = (sp0 < jslot) && (ra0 <= 15.0f);
            bool v1 = has1 && (sp1 < jslot) && (ra1 <= 15.0f);

            float cni0 = pi0.w, cni1 = pi1.w;
            float Dp0 = fmaf(-F_K3L, cni0 * cni0, -Lcnj2);
            float Dp1 = fmaf(-F_K3L, cni1 * cni1, -Lcnj2);

            float wa0 = 0.0f, ca0 = 0.0f, wa1 = 0.0f, ca1 = 0.0f;
            #pragma unroll
            for (int r = 0; r < 25; r++) {
                float4 tv = ptab[r];
                float base = fmaf(tv.y, cnj_v, tv.z);
                float w0 = ex2f(fmaf(tv.x, cni0, base) + Dp0);
                float w1 = ex2f(fmaf(tv.x, cni1, base) + Dp1);
                wa0 += w0; ca0 = fmaf(tv.w, w0, ca0);
                wa1 += w1; ca1 = fmaf(tv.w, w1, ca1);
            }

            // tail i0: e = e(i,j)+e(j,i) (combined numerator, shared wsum)
            {
                float c6v = __fdividef(ca0, wa0 + 1e-20f);
                float rr = rri0 * rrj;
                float c8 = 3.0f * c6v * rr;
                float r0v = sqrtf(3.0f * rr);
                float fv = fmaf(F_A1, r0v, F_A2);
                float f2 = fv * fv;
                float f6 = f2 * f2 * f2;
                float f8 = f6 * f2;
                float rb2 = r2_0 * F_BOHR2;
                float r6 = rb2 * rb2 * rb2;
                float r8 = r6 * rb2;
                float e = __fdividef(c6v, r6 + f6) + F_S8 * __fdividef(c8, r8 + f8);
                float x = __saturatef((ra0 - 12.0f) * (1.0f / 3.0f));
                float sw = 1.0f - x * x * (3.0f - 2.0f * x);
                esum = fmaf(e * sw, v0 ? 1.0f : 0.0f, esum);
            }
            // tail i1
            {
                float c6v = __fdividef(ca1, wa1 + 1e-20f);
                float rr = rri1 * rrj;
                float c8 = 3.0f * c6v * rr;
                float r0v = sqrtf(3.0f * rr);
                float fv = fmaf(F_A1, r0v, F_A2);
                float f2 = fv * fv;
                float f6 = f2 * f2 * f2;
                float f8 = f6 * f2;
                float rb2 = r2_1 * F_BOHR2;
                float r6 = rb2 * rb2 * rb2;
                float r8 = r6 * rb2;
                float e = __fdividef(c6v, r6 + f6) + F_S8 * __fdividef(c8, r8 + f8);
                float x = __saturatef((ra1 - 12.0f) * (1.0f / 3.0f));
                float sw = 1.0f - x * x * (3.0f - 2.0f * x);
                esum = fmaf(e * sw, v1 ? 1.0f : 0.0f, esum);
            }
        }

        // deterministic block reduce -> g_partial[it]
        #pragma unroll
        for (int o = 16; o > 0; o >>= 1) esum += __shfl_down_sync(0xffffffffu, esum, o);
        if (lane == 0) s_red[wid] = esum;
        __syncthreads();
        if (t < 32) {
            float v = (t < 16) ? s_red[t] : 0.0f;
            #pragma unroll
            for (int o = 8; o > 0; o >>= 1) v += __shfl_down_sync(0xffffffffu, v, o);
            if (t == 0) g_partial[it] = v;
        }
    }

    gsync(2);

    // =====================================================================
    // Phase 4: block 0 finalizes (fixed order, double precision). Factor -0.5:
    // each unordered pair contributed e(i,j)+e(j,i). Resets queue.
    // =====================================================================
    if (blk == 0) {
        if (t == 0) g_ticket = 0;              // ready for next graph replay
        for (int b2 = 0; b2 < BB; b2++) {
            double v = 0.0;
            if (t < NZV)
                v = (double)((volatile float*)g_partial)[t * 4 + b2];
            #pragma unroll
            for (int o = 16; o > 0; o >>= 1) v += __shfl_down_sync(0xffffffffu, v, o);
            if (lane == 0) s_dred[wid] = v;
            __syncthreads();
            if (t < 32) {
                double u = (t < 16) ? s_dred[t] : 0.0;
                #pragma unroll
                for (int o = 8; o > 0; o >>= 1) u += __shfl_down_sync(0xffffffffu, u, o);
                if (t == 0) out[b2] = (float)(-0.5 * u * (double)F_H2EV);
            }
            __syncthreads();
        }
    }
}

extern "C" void kernel_launch(void* const* d_in, const int* in_sizes, int n_in,
                              void* d_out, int out_size)
{
    const float* coord   = (const float*)d_in[0];
    const int*   numbers = (const int*)  d_in[1];
    const float* rcov    = (const float*)d_in[2];
    const float* r4r2    = (const float*)d_in[3];
    const float* c6ab    = (const float*)d_in[4];
    const float* cn_ref  = (const float*)d_in[5];
    float* out = (float*)d_out;

    fused_kernel<<<GRID, NT>>>(coord, numbers, rcov, r4r2, c6ab, cn_ref, out);
}